// round 3
// baseline (speedup 1.0000x reference)
#include <cuda_runtime.h>
#include <cstdint>
#include <cstddef>

typedef unsigned long long ull;

#define TS 2048
#define Y1_ELEMS ((size_t)TS * 64 * 256)

// scratch (allocation-free rule)
__device__ float g_gx[(size_t)TS * 64 * 1024];
__device__ float g_y0[(size_t)TS * 64 * 256];

__device__ __forceinline__ ull fma2(ull a, ull b, ull c) {
    ull d; asm("fma.rn.f32x2 %0,%1,%2,%3;" : "=l"(d) : "l"(a), "l"(b), "l"(c)); return d;
}
__device__ __forceinline__ ull add2(ull a, ull b) {
    ull d; asm("add.rn.f32x2 %0,%1,%2;" : "=l"(d) : "l"(a), "l"(b)); return d;
}
__device__ __forceinline__ ull pk(float lo, float hi) {
    ull r; asm("mov.b64 %0,{%1,%2};" : "=l"(r) : "f"(lo), "f"(hi)); return r;
}
__device__ __forceinline__ void upk(ull a, float& x, float& y) {
    asm("mov.b64 {%0,%1},%2;" : "=f"(x), "=f"(y) : "l"(a));
}
__device__ __forceinline__ ull dup2(float x) {
    ull r; asm("mov.b64 %0,{%1,%1};" : "=l"(r) : "f"(x)); return r;
}
__device__ __forceinline__ float sigf(float x) {
    return __fdividef(1.f, 1.f + __expf(-x));
}

// ---------------------------------------------------------------------------
// GEMM: g_gx[m][n] = A_row(m) . W[:,n] + bias[n],  M = TS*64, N = 1024
// mode 0: A_row(m) = x + ((m&63)*TS + (m>>6))*128, K=128
// mode 1: A_row(m) = g_y0 + m*256,                 K=256
// ---------------------------------------------------------------------------
__global__ void __launch_bounds__(256, 1)
gemm_k(const float* __restrict__ A, const float* __restrict__ W,
       const float* __restrict__ bias, int K, int mode)
{
    __shared__ float As[16][132];
    __shared__ float Bs[16][128];

    const int tid = threadIdx.x;
    const int n0 = blockIdx.x * 128;
    const int m0 = blockIdx.y * 128;

    // A loader: row ar, 8 cols starting at ac
    const int ar = tid >> 1;
    const int ac = (tid & 1) * 8;
    const int m = m0 + ar;
    const float* arow = mode ? (g_y0 + (size_t)m * 256)
                             : (A + ((size_t)(m & 63) * TS + (m >> 6)) * 128);
    // W loader: row (tid>>4), 8 cols at (tid&15)*8
    const float* wp = W + (size_t)(tid >> 4) * 1024 + n0 + (tid & 15) * 8;

    const int tm = tid >> 4, tn = tid & 15;

    ull acc[8][4];
#pragma unroll
    for (int i = 0; i < 8; ++i)
#pragma unroll
        for (int j = 0; j < 4; ++j) acc[i][j] = 0ull;

#pragma unroll 1
    for (int k0 = 0; k0 < K; k0 += 16) {
        float4 a0 = *(const float4*)(arow + k0 + ac);
        float4 a1 = *(const float4*)(arow + k0 + ac + 4);
        float4 w0 = *(const float4*)(wp + (size_t)k0 * 1024);
        float4 w1 = *(const float4*)(wp + (size_t)k0 * 1024 + 4);
        __syncthreads();
        As[ac + 0][ar] = a0.x; As[ac + 1][ar] = a0.y;
        As[ac + 2][ar] = a0.z; As[ac + 3][ar] = a0.w;
        As[ac + 4][ar] = a1.x; As[ac + 5][ar] = a1.y;
        As[ac + 6][ar] = a1.z; As[ac + 7][ar] = a1.w;
        *(float4*)&Bs[tid >> 4][(tid & 15) * 8] = w0;
        *(float4*)&Bs[tid >> 4][(tid & 15) * 8 + 4] = w1;
        __syncthreads();
#pragma unroll
        for (int kk = 0; kk < 16; ++kk) {
            float4 av0 = *(const float4*)&As[kk][tm * 8];
            float4 av1 = *(const float4*)&As[kk][tm * 8 + 4];
            float av[8] = {av0.x, av0.y, av0.z, av0.w, av1.x, av1.y, av1.z, av1.w};
            const ull* bp = (const ull*)&Bs[kk][0];
            ull bv[4];
#pragma unroll
            for (int c = 0; c < 4; ++c) bv[c] = bp[tn * 4 + c];
#pragma unroll
            for (int r = 0; r < 8; ++r) {
                ull a2 = dup2(av[r]);
#pragma unroll
                for (int c = 0; c < 4; ++c) acc[r][c] = fma2(a2, bv[c], acc[r][c]);
            }
        }
    }

    float bb[8];
#pragma unroll
    for (int c = 0; c < 8; ++c) bb[c] = bias[n0 + tn * 8 + c];

#pragma unroll
    for (int r = 0; r < 8; ++r) {
        float v[8];
#pragma unroll
        for (int c = 0; c < 4; ++c) upk(acc[r][c], v[2 * c], v[2 * c + 1]);
#pragma unroll
        for (int c = 0; c < 8; ++c) v[c] += bb[c];
        float* op = g_gx + (size_t)(m0 + tm * 8 + r) * 1024 + n0 + tn * 8;
        *(float4*)op = make_float4(v[0], v[1], v[2], v[3]);
        *(float4*)(op + 4) = make_float4(v[4], v[5], v[6], v[7]);
    }
}

// ---------------------------------------------------------------------------
// Recurrence: 16 clusters x 8 CTAs. Cluster handles 4 batch elems.
// CTA rank r owns hidden units j in [r*32, r*32+32) (all 4 gates = 128 cols).
// Thread (q = tid>>6, c = tid&63): gate = c>>4, j0 = r*32 + (c&15)*2;
// owns cols (gate,j0),(gate,j0+1) over k in [q*64, q*64+64), k-pair packed.
// ---------------------------------------------------------------------------
__global__ void __launch_bounds__(256, 1) __cluster_dims__(8, 1, 1)
recur_k(const float* __restrict__ whh, float* __restrict__ out, int layer)
{
    __shared__ float2 hbuf[2][4][128];   // [buf][b][kpair]
    __shared__ ull red[4][4][128];       // [q][b][gate*32 + jl]

    const int tid = threadIdx.x;
    const int q = tid >> 6;
    const int c = tid & 63;
    unsigned r;
    asm("mov.u32 %0, %%cluster_ctarank;" : "=r"(r));
    const int gb0 = (blockIdx.x >> 3) * 4;

    const int gate = c >> 4;
    const int j0 = (int)r * 32 + (c & 15) * 2;
    const int col = gate * 256 + j0;

    // load w_hh slice into registers, k-pair packed
    ull wa[32], wb[32];
#pragma unroll
    for (int kk = 0; kk < 32; ++kk) {
        const float* w0 = whh + (size_t)(q * 64 + 2 * kk) * 1024 + col;
        wa[kk] = pk(w0[0], w0[1024]);
        wb[kk] = pk(w0[1], w0[1025]);
    }

    // zero h buffers
    for (int i = tid; i < 2 * 4 * 128; i += 256)
        ((float2*)hbuf)[i] = make_float2(0.f, 0.f);
    __syncthreads();

    const int eb = tid >> 5, ejl = tid & 31;      // epilogue id (tid<128)
    const int ej = (int)r * 32 + ejl;
    float cst = 0.f;
    float* yout = layer ? out : g_y0;
    float* hn = out + Y1_ELEMS + (size_t)layer * 16384;
    float* cn = out + Y1_ELEMS + 32768 + (size_t)layer * 16384;
    unsigned hb;
    {
        size_t gp = __cvta_generic_to_shared(&hbuf[0][0][0]);
        hb = (unsigned)gp;
    }

    int cur = 0;
#pragma unroll 1
    for (int s = 0; s < TS; ++s) {
        // prefetch gates_x for epilogue
        float gf = 0.f, gi = 0.f, go = 0.f, gg = 0.f;
        if (tid < 128) {
            const float* gp = g_gx + ((size_t)(TS - 1 - s) * 64 + gb0 + eb) * 1024 + ej;
            gf = gp[0]; gi = gp[256]; go = gp[512]; gg = gp[768];
        }
        // matvec
#pragma unroll
        for (int b = 0; b < 4; ++b) {
            const ull* hp = (const ull*)&hbuf[cur][b][0] + q * 32;
            ull a0 = 0ull, a1 = 0ull;
#pragma unroll
            for (int kk = 0; kk < 32; ++kk) {
                ull hh = hp[kk];
                a0 = fma2(hh, wa[kk], a0);
                a1 = fma2(hh, wb[kk], a1);
            }
            red[q][b][gate * 32 + (c & 15) * 2] = a0;
            red[q][b][gate * 32 + (c & 15) * 2 + 1] = a1;
        }
        __syncthreads();

        const int nxt = cur ^ 1;
        if (tid < 128) {
            float gates[4];
#pragma unroll
            for (int g = 0; g < 4; ++g) {
                ull s01 = add2(red[0][eb][g * 32 + ejl], red[1][eb][g * 32 + ejl]);
                ull s23 = add2(red[2][eb][g * 32 + ejl], red[3][eb][g * 32 + ejl]);
                float lo, hi; upk(add2(s01, s23), lo, hi);
                gates[g] = lo + hi;
            }
            float f = sigf(gates[0] + gf);
            float i = sigf(gates[1] + gi);
            float o = sigf(gates[2] + go);
            float g_ = tanhf(gates[3] + gg);
            cst = f * cst + i * g_;
            float h1 = o * tanhf(cst);

            yout[((size_t)s * 64 + gb0 + eb) * 256 + ej] = h1;
            if (s == TS - 1) {
                size_t hi_ = (size_t)(gb0 + eb) * 256 + ej;
                hn[hi_] = h1; cn[hi_] = cst;
            }
            // push h1 to all 8 CTAs' hbuf[nxt][eb][ej]
            unsigned laddr = hb + (unsigned)(((nxt * 4 + eb) * 256 + ej) * 4);
#pragma unroll
            for (unsigned dr = 0; dr < 8; ++dr) {
                unsigned ra;
                asm("mapa.shared::cluster.u32 %0, %1, %2;" : "=r"(ra) : "r"(laddr), "r"(dr));
                asm volatile("st.shared::cluster.f32 [%0], %1;" :: "r"(ra), "f"(h1));
            }
        }
        asm volatile("barrier.cluster.arrive.aligned;" ::: "memory");
        asm volatile("barrier.cluster.wait.aligned;" ::: "memory");
        cur ^= 1;
    }
}

extern "C" void kernel_launch(void* const* d_in, const int* in_sizes, int n_in,
                              void* d_out, int out_size)
{
    const float* x    = (const float*)d_in[0];
    const float* wih0 = (const float*)d_in[1];
    const float* whh0 = (const float*)d_in[2];
    const float* b0   = (const float*)d_in[3];
    const float* wih1 = (const float*)d_in[4];
    const float* whh1 = (const float*)d_in[5];
    const float* b1   = (const float*)d_in[6];
    float* out = (float*)d_out;

    dim3 gg(8, 1024);
    gemm_k<<<gg, 256>>>(x, wih0, b0, 128, 0);
    recur_k<<<128, 256>>>(whh0, out, 0);
    gemm_k<<<gg, 256>>>(x, wih1, b1, 256, 1);
    recur_k<<<128, 256>>>(whh1, out, 1);
}